// round 1
// baseline (speedup 1.0000x reference)
#include <cuda_runtime.h>

#define IDIM 1024
#define ODIM 1024
#define NDEG 9            // degree 8 -> 9 coefficients
#define KDIM (IDIM*NDEG)  // 9216
#define BMAX 8192

// Scratch (static device globals: allocation-guard safe)
__device__ float g_T[(size_t)BMAX * KDIM];    // T basis, [B][K], K = i*9+j
__device__ float g_Bt[(size_t)KDIM * ODIM];   // coeffs transposed to [K][O]
__device__ float g_mn[BMAX];
__device__ float g_sc[BMAX];

// ---------------------------------------------------------------------------
// Kernel 1: per-row min/max -> min and scale = 2/(max-min)
// ---------------------------------------------------------------------------
__global__ void rowstats_kernel(const float* __restrict__ x) {
    int b = blockIdx.x;
    const float* row = x + (size_t)b * IDIM;
    float mn = 1e30f, mx = -1e30f;
    for (int i = threadIdx.x; i < IDIM; i += blockDim.x) {
        float v = row[i];
        mn = fminf(mn, v);
        mx = fmaxf(mx, v);
    }
    #pragma unroll
    for (int o = 16; o; o >>= 1) {
        mn = fminf(mn, __shfl_xor_sync(0xFFFFFFFFu, mn, o));
        mx = fmaxf(mx, __shfl_xor_sync(0xFFFFFFFFu, mx, o));
    }
    __shared__ float smn[8], smx[8];
    int w = threadIdx.x >> 5, l = threadIdx.x & 31;
    if (l == 0) { smn[w] = mn; smx[w] = mx; }
    __syncthreads();
    if (threadIdx.x == 0) {
        #pragma unroll
        for (int i = 1; i < 8; i++) {
            mn = fminf(mn, smn[i]);
            mx = fmaxf(mx, smx[i]);
        }
        g_mn[b] = mn;
        g_sc[b] = 2.0f / (mx - mn);
    }
}

// ---------------------------------------------------------------------------
// Kernel 2: build Chebyshev basis T[b][i*9+j]
// ---------------------------------------------------------------------------
__global__ void buildT_kernel(const float* __restrict__ x, int total) {
    int idx = blockIdx.x * blockDim.x + threadIdx.x;
    if (idx >= total) return;
    int b = idx >> 10;       // / IDIM
    int i = idx & 1023;      // % IDIM
    float xn = (x[idx] - g_mn[b]) * g_sc[b] - 1.0f;
    float* out = g_T + (size_t)b * KDIM + i * NDEG;
    float t0 = 1.0f, t1 = xn;
    out[0] = t0;
    out[1] = t1;
    #pragma unroll
    for (int j = 2; j < NDEG; j++) {
        float t2 = 2.0f * xn * t1 - t0;
        out[j] = t2;
        t0 = t1;
        t1 = t2;
    }
}

// ---------------------------------------------------------------------------
// Kernel 3: transpose coeffs [i][o][j] -> Bt[k = i*9+j][o]
// ---------------------------------------------------------------------------
__global__ void transC_kernel(const float* __restrict__ c) {
    int idx = blockIdx.x * blockDim.x + threadIdx.x;
    if (idx >= IDIM * ODIM * NDEG) return;
    int j = idx % NDEG;
    int t = idx / NDEG;
    int o = t % ODIM;
    int i = t / ODIM;
    g_Bt[(size_t)(i * NDEG + j) * ODIM + o] = c[idx];
}

// ---------------------------------------------------------------------------
// Kernel 4: SGEMM  out[M,O] = T[M,K] * Bt[K,O]   with packed f32x2 FMA
// ---------------------------------------------------------------------------
#define BM 128
#define BN 128
#define BK 16
#define TM 8
#define TN 8

typedef unsigned long long u64;

__device__ __forceinline__ u64 pack2(float lo, float hi) {
    u64 r;
    asm("mov.b64 %0, {%1, %2};" : "=l"(r) : "f"(lo), "f"(hi));
    return r;
}
__device__ __forceinline__ void fma2(u64& d, u64 a, u64 b) {
    asm("fma.rn.f32x2 %0, %1, %2, %0;" : "+l"(d) : "l"(a), "l"(b));
}

__global__ __launch_bounds__(256, 2) void gemm_kernel(float* __restrict__ out) {
    __shared__ float As[BK][BM];   // transposed A tile
    __shared__ float Bs[BK][BN];

    int tid = threadIdx.x;
    int tx = tid & 15;       // n direction, 16 threads
    int ty = tid >> 4;       // m direction, 16 threads
    int mBase = blockIdx.y * BM;
    int nBase = blockIdx.x * BN;

    const float* Ag = g_T + (size_t)mBase * KDIM;
    const float* Bg = g_Bt + nBase;

    // A tile: 128 rows x 16 cols = 512 float4; f = tid + 256*s
    int arow0 = tid >> 2;
    int akc = (tid & 3) * 4;
    // B tile: 16 rows x 128 cols = 512 float4
    int brow0 = tid >> 5;
    int bnc = (tid & 31) * 4;

    float4 aReg[2], bReg[2];
    #pragma unroll
    for (int s = 0; s < 2; s++) {
        aReg[s] = *(const float4*)(Ag + (size_t)(arow0 + s * 64) * KDIM + akc);
        bReg[s] = *(const float4*)(Bg + (size_t)(brow0 + s * 8) * ODIM + bnc);
    }

    u64 acc[TM][TN / 2];
    #pragma unroll
    for (int m = 0; m < TM; m++)
        #pragma unroll
        for (int j = 0; j < TN / 2; j++)
            acc[m][j] = 0ull;

    const int nk = KDIM / BK;   // 576
    for (int kt = 0; kt < nk; kt++) {
        // commit prefetched tile to smem
        #pragma unroll
        for (int s = 0; s < 2; s++) {
            int arow = arow0 + s * 64;
            As[akc + 0][arow] = aReg[s].x;
            As[akc + 1][arow] = aReg[s].y;
            As[akc + 2][arow] = aReg[s].z;
            As[akc + 3][arow] = aReg[s].w;
            *(float4*)&Bs[brow0 + s * 8][bnc] = bReg[s];
        }
        __syncthreads();

        // prefetch next tile (latency hidden under compute)
        if (kt + 1 < nk) {
            int kOff = (kt + 1) * BK;
            #pragma unroll
            for (int s = 0; s < 2; s++) {
                aReg[s] = *(const float4*)(Ag + (size_t)(arow0 + s * 64) * KDIM + kOff + akc);
                bReg[s] = *(const float4*)(Bg + (size_t)(kOff + brow0 + s * 8) * ODIM + bnc);
            }
        }

        #pragma unroll
        for (int kk = 0; kk < BK; kk++) {
            float4 a0 = *(const float4*)&As[kk][ty * TM];
            float4 a1 = *(const float4*)&As[kk][ty * TM + 4];
            float4 b0 = *(const float4*)&Bs[kk][tx * TN];
            float4 b1 = *(const float4*)&Bs[kk][tx * TN + 4];
            u64 b2[4];
            b2[0] = pack2(b0.x, b0.y);
            b2[1] = pack2(b0.z, b0.w);
            b2[2] = pack2(b1.x, b1.y);
            b2[3] = pack2(b1.z, b1.w);
            float av[8] = {a0.x, a0.y, a0.z, a0.w, a1.x, a1.y, a1.z, a1.w};
            #pragma unroll
            for (int m = 0; m < TM; m++) {
                u64 aa = pack2(av[m], av[m]);
                #pragma unroll
                for (int j = 0; j < TN / 2; j++)
                    fma2(acc[m][j], aa, b2[j]);
            }
        }
        __syncthreads();
    }

    // epilogue
    #pragma unroll
    for (int m = 0; m < TM; m++) {
        float* orow = out + (size_t)(mBase + ty * TM + m) * ODIM + nBase + tx * TN;
        float lo0, hi0, lo1, hi1, lo2, hi2, lo3, hi3;
        asm("mov.b64 {%0, %1}, %2;" : "=f"(lo0), "=f"(hi0) : "l"(acc[m][0]));
        asm("mov.b64 {%0, %1}, %2;" : "=f"(lo1), "=f"(hi1) : "l"(acc[m][1]));
        asm("mov.b64 {%0, %1}, %2;" : "=f"(lo2), "=f"(hi2) : "l"(acc[m][2]));
        asm("mov.b64 {%0, %1}, %2;" : "=f"(lo3), "=f"(hi3) : "l"(acc[m][3]));
        *(float4*)(orow)     = make_float4(lo0, hi0, lo1, hi1);
        *(float4*)(orow + 4) = make_float4(lo2, hi2, lo3, hi3);
    }
}

// ---------------------------------------------------------------------------
extern "C" void kernel_launch(void* const* d_in, const int* in_sizes, int n_in,
                              void* d_out, int out_size) {
    const float* x = (const float*)d_in[0];
    const float* coeffs = (const float*)d_in[1];
    float* out = (float*)d_out;

    int nb = in_sizes[0] / IDIM;   // 8192

    rowstats_kernel<<<nb, 256>>>(x);

    int totalT = nb * IDIM;
    buildT_kernel<<<(totalT + 255) / 256, 256>>>(x, totalT);

    int totalC = IDIM * ODIM * NDEG;
    transC_kernel<<<(totalC + 255) / 256, 256>>>(coeffs);

    dim3 grid(ODIM / BN, nb / BM);   // (8, 64)
    gemm_kernel<<<grid, 256>>>(out);
}

// round 4
// speedup vs baseline: 2.0493x; 2.0493x over previous
#include <cuda_runtime.h>
#include <cuda_bf16.h>
#include <cstdint>

#define IDIM 1024
#define ODIM 1024
#define NDEG 9
#define KDIM (IDIM*NDEG)   // 9216
#define BMAX 8192

// ---------------- device scratch (static globals: allocation-guard safe) ----
__device__ __nv_bfloat16 g_Th[(size_t)BMAX * KDIM];   // A hi  [M][K]
__device__ __nv_bfloat16 g_Tl[(size_t)BMAX * KDIM];   // A lo  [M][K]
__device__ __nv_bfloat16 g_Bh[(size_t)ODIM * KDIM];   // B hi  [N][K]
__device__ __nv_bfloat16 g_Bl[(size_t)ODIM * KDIM];   // B lo  [N][K]
__device__ float g_mn[BMAX];
__device__ float g_sc[BMAX];

// ---------------------------------------------------------------------------
// Kernel 1: per-row min/max
// ---------------------------------------------------------------------------
__global__ void rowstats_kernel(const float* __restrict__ x) {
    int b = blockIdx.x;
    const float* row = x + (size_t)b * IDIM;
    float mn = 1e30f, mx = -1e30f;
    for (int i = threadIdx.x; i < IDIM; i += blockDim.x) {
        float v = row[i];
        mn = fminf(mn, v);
        mx = fmaxf(mx, v);
    }
    #pragma unroll
    for (int o = 16; o; o >>= 1) {
        mn = fminf(mn, __shfl_xor_sync(0xFFFFFFFFu, mn, o));
        mx = fmaxf(mx, __shfl_xor_sync(0xFFFFFFFFu, mx, o));
    }
    __shared__ float smn[8], smx[8];
    int w = threadIdx.x >> 5, l = threadIdx.x & 31;
    if (l == 0) { smn[w] = mn; smx[w] = mx; }
    __syncthreads();
    if (threadIdx.x == 0) {
        #pragma unroll
        for (int i = 1; i < 8; i++) { mn = fminf(mn, smn[i]); mx = fmaxf(mx, smx[i]); }
        g_mn[b] = mn;
        g_sc[b] = 2.0f / (mx - mn);
    }
}

// ---------------------------------------------------------------------------
// Kernel 2: build Chebyshev basis, hi/lo bf16 split
// ---------------------------------------------------------------------------
__global__ void buildT_kernel(const float* __restrict__ x, int total) {
    int idx = blockIdx.x * blockDim.x + threadIdx.x;
    if (idx >= total) return;
    int b = idx >> 10;
    int i = idx & 1023;
    float xn = (x[idx] - g_mn[b]) * g_sc[b] - 1.0f;
    size_t off = (size_t)b * KDIM + i * NDEG;
    float t0 = 1.0f, t1 = xn;
    float tv[NDEG];
    tv[0] = t0; tv[1] = t1;
    #pragma unroll
    for (int j = 2; j < NDEG; j++) {
        float t2 = 2.0f * xn * t1 - t0;
        tv[j] = t2; t0 = t1; t1 = t2;
    }
    #pragma unroll
    for (int j = 0; j < NDEG; j++) {
        __nv_bfloat16 h = __float2bfloat16(tv[j]);
        float hf = __bfloat162float(h);
        g_Th[off + j] = h;
        g_Tl[off + j] = __float2bfloat16(tv[j] - hf);
    }
}

// ---------------------------------------------------------------------------
// Kernel 3: coeffs [i][o][j] -> B[o][k=i*9+j], hi/lo bf16
// ---------------------------------------------------------------------------
__global__ void transC_kernel(const float* __restrict__ c) {
    int idx = blockIdx.x * blockDim.x + threadIdx.x;
    if (idx >= IDIM * ODIM) return;
    int i = idx & 1023;
    int o = idx >> 10;
    const float* src = c + ((size_t)i * ODIM + o) * NDEG;
    size_t dst = (size_t)o * KDIM + i * NDEG;
    #pragma unroll
    for (int j = 0; j < NDEG; j++) {
        float v = src[j];
        __nv_bfloat16 h = __float2bfloat16(v);
        float hf = __bfloat162float(h);
        g_Bh[dst + j] = h;
        g_Bl[dst + j] = __float2bfloat16(v - hf);
    }
}

// ---------------------------------------------------------------------------
// Kernel 4: mma.sync bf16 GEMM, CTA 128x256, warp 64x64, BK=32, 3 splits
// ---------------------------------------------------------------------------
#define TILE_M 128
#define TILE_N 256
#define BK 32
#define NK (KDIM / BK)        // 288
#define ROWP 40               // padded row stride (elements); 80B, conflict-free
#define A_SPLIT_BYTES (TILE_M * ROWP * 2)   // 10240
#define B_SPLIT_BYTES (TILE_N * ROWP * 2)   // 20480
#define STAGE_BYTES (2*A_SPLIT_BYTES + 2*B_SPLIT_BYTES)   // 61440
#define SMEM_TOTAL (2 * STAGE_BYTES)                      // 122880

__device__ __forceinline__ uint32_t smem_u32(const void* p) {
    uint32_t a;
    asm("{ .reg .u64 t; cvta.to.shared.u64 t, %1; cvt.u32.u64 %0, t; }"
        : "=r"(a) : "l"(p));
    return a;
}
__device__ __forceinline__ void cp16(uint32_t dst, const void* src) {
    asm volatile("cp.async.cg.shared.global [%0], [%1], 16;" :: "r"(dst), "l"(src));
}
__device__ __forceinline__ void ldmx4(uint32_t* r, uint32_t addr) {
    asm volatile("ldmatrix.sync.aligned.m8n8.x4.shared.b16 {%0,%1,%2,%3}, [%4];"
                 : "=r"(r[0]), "=r"(r[1]), "=r"(r[2]), "=r"(r[3]) : "r"(addr));
}
__device__ __forceinline__ void mma16816(float* c, const uint32_t* a, const uint32_t* b) {
    asm volatile(
        "mma.sync.aligned.m16n8k16.row.col.f32.bf16.bf16.f32 "
        "{%0,%1,%2,%3}, {%4,%5,%6,%7}, {%8,%9}, {%0,%1,%2,%3};"
        : "+f"(c[0]), "+f"(c[1]), "+f"(c[2]), "+f"(c[3])
        : "r"(a[0]), "r"(a[1]), "r"(a[2]), "r"(a[3]), "r"(b[0]), "r"(b[1]));
}

extern __shared__ char dynsmem[];

__global__ void __launch_bounds__(256, 1) gemm_mma_kernel(float* __restrict__ out) {
    const uint32_t smem_base = smem_u32(dynsmem);
    const int tid = threadIdx.x;
    const int lane = tid & 31;
    const int warp = tid >> 5;
    const int wm = warp >> 2;        // 0..1  -> M offset 64*wm
    const int wn = warp & 3;         // 0..3  -> N offset 64*wn

    const int mBase = blockIdx.y * TILE_M;
    const int nBase = blockIdx.x * TILE_N;

    const __nv_bfloat16* Asrc[2] = { g_Th + (size_t)mBase * KDIM,
                                     g_Tl + (size_t)mBase * KDIM };
    const __nv_bfloat16* Bsrc[2] = { g_Bh + (size_t)nBase * KDIM,
                                     g_Bl + (size_t)nBase * KDIM };

    // per-thread cp.async chunk coords
    // A: 1024 chunks: c = tid + 256*r (r<4): split=c>>9, row=(c>>2)&127, kc=c&3
    // B: 2048 chunks: c = tid + 256*r (r<8): split=c>>10, row=(c>>2)&255, kc=c&3
    // ldmatrix lane addressing (non-trans for both operands)
    const int aRow = (lane & 7) + ((lane >> 3) & 1) * 8;   // row within m16
    const int aK8  = (lane >> 4) & 1;                       // k +8 select
    const int bRow = (lane & 7) + ((lane >> 4) & 1) * 8;   // row within n16
    const int bK8  = (lane >> 3) & 1;

    float acc[4][8][4];
    #pragma unroll
    for (int mt = 0; mt < 4; mt++)
        #pragma unroll
        for (int nt = 0; nt < 8; nt++)
            #pragma unroll
            for (int j = 0; j < 4; j++)
                acc[mt][nt][j] = 0.0f;

    // ---- stage loader -------------------------------------------------
    auto load_stage = [&](int kt, int buf) {
        const int k0 = kt * BK;
        const uint32_t so = smem_base + buf * STAGE_BYTES;
        #pragma unroll
        for (int r = 0; r < 4; r++) {
            int c = tid + 256 * r;
            int s = c >> 9, row = (c >> 2) & 127, kc = c & 3;
            cp16(so + s * A_SPLIT_BYTES + row * (ROWP * 2) + kc * 16,
                 Asrc[s] + (size_t)row * KDIM + k0 + kc * 8);
        }
        #pragma unroll
        for (int r = 0; r < 8; r++) {
            int c = tid + 256 * r;
            int s = c >> 10, row = (c >> 2) & 255, kc = c & 3;
            cp16(so + 2 * A_SPLIT_BYTES + s * B_SPLIT_BYTES + row * (ROWP * 2) + kc * 16,
                 Bsrc[s] + (size_t)row * KDIM + k0 + kc * 8);
        }
        asm volatile("cp.async.commit_group;" ::: "memory");
    };

    load_stage(0, 0);

    for (int kt = 0; kt < NK; kt++) {
        const int buf = kt & 1;
        if (kt + 1 < NK) {
            load_stage(kt + 1, buf ^ 1);
            asm volatile("cp.async.wait_group 1;" ::: "memory");
        } else {
            asm volatile("cp.async.wait_group 0;" ::: "memory");
        }
        __syncthreads();

        const uint32_t so = smem_base + buf * STAGE_BYTES;
        const uint32_t aBase = so + ((wm * 64 + aRow) * ROWP + aK8 * 8) * 2;
        const uint32_t bBase = so + 2 * A_SPLIT_BYTES
                             + ((wn * 64 + bRow) * ROWP + bK8 * 8) * 2;

        #pragma unroll
        for (int kk = 0; kk < BK; kk += 16) {
            uint32_t af[2][4][4];
            uint32_t bf[2][8][2];
            #pragma unroll
            for (int s = 0; s < 2; s++) {
                #pragma unroll
                for (int mt = 0; mt < 4; mt++)
                    ldmx4(af[s][mt], aBase + s * A_SPLIT_BYTES
                                   + (mt * 16 * ROWP + kk) * 2);
                #pragma unroll
                for (int nt2 = 0; nt2 < 4; nt2++) {
                    uint32_t r[4];
                    ldmx4(r, bBase + s * B_SPLIT_BYTES
                           + (nt2 * 16 * ROWP + kk) * 2);
                    bf[s][nt2 * 2 + 0][0] = r[0];
                    bf[s][nt2 * 2 + 0][1] = r[1];
                    bf[s][nt2 * 2 + 1][0] = r[2];
                    bf[s][nt2 * 2 + 1][1] = r[3];
                }
            }
            // 3 split combos: (Ah,Bh), (Ah,Bl), (Al,Bh)
            #pragma unroll
            for (int mt = 0; mt < 4; mt++)
                #pragma unroll
                for (int nt = 0; nt < 8; nt++) {
                    mma16816(acc[mt][nt], af[0][mt], bf[0][nt]);
                    mma16816(acc[mt][nt], af[0][mt], bf[1][nt]);
                    mma16816(acc[mt][nt], af[1][mt], bf[0][nt]);
                }
        }
        __syncthreads();
    }

    // ---- epilogue ------------------------------------------------------
    const int mW = mBase + wm * 64;
    const int nW = nBase + wn * 64;
    #pragma unroll
    for (int mt = 0; mt < 4; mt++) {
        #pragma unroll
        for (int nt = 0; nt < 8; nt++) {
            int row0 = mW + mt * 16 + (lane >> 2);
            int col  = nW + nt * 8 + (lane & 3) * 2;
            float2 v0 = make_float2(acc[mt][nt][0], acc[mt][nt][1]);
            float2 v1 = make_float2(acc[mt][nt][2], acc[mt][nt][3]);
            *(float2*)(out + (size_t)row0 * ODIM + col) = v0;
            *(float2*)(out + (size_t)(row0 + 8) * ODIM + col) = v1;
        }
    }
}

// ---------------------------------------------------------------------------
extern "C" void kernel_launch(void* const* d_in, const int* in_sizes, int n_in,
                              void* d_out, int out_size) {
    const float* x = (const float*)d_in[0];
    const float* coeffs = (const float*)d_in[1];
    float* out = (float*)d_out;

    int nb = in_sizes[0] / IDIM;   // 8192

    cudaFuncSetAttribute(gemm_mma_kernel,
                         cudaFuncAttributeMaxDynamicSharedMemorySize, SMEM_TOTAL);

    rowstats_kernel<<<nb, 256>>>(x);

    int totalT = nb * IDIM;
    buildT_kernel<<<(totalT + 255) / 256, 256>>>(x, totalT);

    transC_kernel<<<(IDIM * ODIM + 255) / 256, 256>>>(coeffs);

    dim3 grid(ODIM / TILE_N, nb / TILE_M);   // (4, 64)
    gemm_mma_kernel<<<grid, 256, SMEM_TOTAL>>>(out);
}

// round 7
// speedup vs baseline: 2.4848x; 1.2125x over previous
#include <cuda_runtime.h>
#include <cuda_bf16.h>
#include <cstdint>

#define IDIM 1024
#define ODIM 1024
#define NDEG 9
#define KDIM (IDIM*NDEG)   // 9216, virtual k = j*1024 + i
#define BMAX 8192

// ---------------- device scratch (static globals: allocation-guard safe) ----
__device__ __nv_bfloat16 g_Th[(size_t)BMAX * KDIM];   // A hi  [M][K]
__device__ __nv_bfloat16 g_Tl[(size_t)BMAX * KDIM];   // A lo  [M][K]
__device__ __nv_bfloat16 g_Bh[(size_t)ODIM * KDIM];   // B hi  [N][K]
__device__ __nv_bfloat16 g_Bl[(size_t)ODIM * KDIM];   // B lo  [N][K]

// ---------------------------------------------------------------------------
// Kernel 1: fused row min/max + Chebyshev basis (hi/lo bf16), K = j*1024 + i
// one block (256 thr) per batch row; bf16x2 coalesced stores
// ---------------------------------------------------------------------------
__global__ void __launch_bounds__(256) buildT_kernel(const float* __restrict__ x) {
    const int b = blockIdx.x;
    const int tid = threadIdx.x;
    const float* row = x + (size_t)b * IDIM;

    // load 4 values (2 float2 pairs) per thread
    float2 v[2];
    #pragma unroll
    for (int s = 0; s < 2; s++)
        v[s] = *(const float2*)(row + 2 * (tid + 256 * s));

    float mn = fminf(fminf(v[0].x, v[0].y), fminf(v[1].x, v[1].y));
    float mx = fmaxf(fmaxf(v[0].x, v[0].y), fmaxf(v[1].x, v[1].y));
    #pragma unroll
    for (int o = 16; o; o >>= 1) {
        mn = fminf(mn, __shfl_xor_sync(0xFFFFFFFFu, mn, o));
        mx = fmaxf(mx, __shfl_xor_sync(0xFFFFFFFFu, mx, o));
    }
    __shared__ float smn[8], smx[8];
    int w = tid >> 5, l = tid & 31;
    if (l == 0) { smn[w] = mn; smx[w] = mx; }
    __syncthreads();
    #pragma unroll
    for (int i = 0; i < 8; i++) { mn = fminf(mn, smn[i]); mx = fmaxf(mx, smx[i]); }
    const float sc = 2.0f / (mx - mn);

    const size_t base = (size_t)b * KDIM;
    #pragma unroll
    for (int s = 0; s < 2; s++) {
        int p = tid + 256 * s;          // pair index; i = 2p, 2p+1
        float xa = (v[s].x - mn) * sc - 1.0f;
        float xb = (v[s].y - mn) * sc - 1.0f;
        float a0 = 1.0f, a1 = xa, b0 = 1.0f, b1 = xb;
        #pragma unroll
        for (int j = 0; j < NDEG; j++) {
            float ta = (j == 0) ? 1.0f : (j == 1 ? xa : a1);
            float tb = (j == 0) ? 1.0f : (j == 1 ? xb : b1);
            if (j >= 1) {
                // recurrence advance for next j
            }
            __nv_bfloat16 ha = __float2bfloat16(ta);
            __nv_bfloat16 hb = __float2bfloat16(tb);
            float la = ta - __bfloat162float(ha);
            float lb = tb - __bfloat162float(hb);
            __nv_bfloat162 hi2, lo2;
            hi2.x = ha; hi2.y = hb;
            lo2.x = __float2bfloat16(la); lo2.y = __float2bfloat16(lb);
            size_t off = base + (size_t)j * IDIM + 2 * p;
            *(__nv_bfloat162*)(g_Th + off) = hi2;
            *(__nv_bfloat162*)(g_Tl + off) = lo2;
            if (j >= 1) {
                float na = 2.0f * xa * a1 - a0; a0 = a1; a1 = na;
                float nb = 2.0f * xb * b1 - b0; b0 = b1; b1 = nb;
            }
        }
    }
}

// ---------------------------------------------------------------------------
// Kernel 2: coeffs [i][o][j] -> B[o][k=j*1024+i], hi/lo bf16, bf16x2 stores
// ---------------------------------------------------------------------------
__global__ void transC_kernel(const float* __restrict__ c) {
    int idx = blockIdx.x * blockDim.x + threadIdx.x;   // ODIM * IDIM/2 threads
    if (idx >= ODIM * (IDIM / 2)) return;
    int o = idx >> 9;
    int p = idx & 511;                  // i = 2p, 2p+1
    const float* s0 = c + ((size_t)(2 * p) * ODIM + o) * NDEG;
    const float* s1 = c + ((size_t)(2 * p + 1) * ODIM + o) * NDEG;
    size_t base = (size_t)o * KDIM + 2 * p;
    #pragma unroll
    for (int j = 0; j < NDEG; j++) {
        float va = s0[j], vb = s1[j];
        __nv_bfloat16 ha = __float2bfloat16(va);
        __nv_bfloat16 hb = __float2bfloat16(vb);
        __nv_bfloat162 hi2, lo2;
        hi2.x = ha; hi2.y = hb;
        lo2.x = __float2bfloat16(va - __bfloat162float(ha));
        lo2.y = __float2bfloat16(vb - __bfloat162float(hb));
        size_t off = base + (size_t)j * IDIM;
        *(__nv_bfloat162*)(g_Bh + off) = hi2;
        *(__nv_bfloat162*)(g_Bl + off) = lo2;
    }
}

// ---------------------------------------------------------------------------
// Kernel 3: mma.sync bf16 GEMM over virtual K' = 3*KDIM
// CTA 128x256, 512 threads, warp tile 32x64, 3-stage cp.async
// ---------------------------------------------------------------------------
#define TILE_M 128
#define TILE_N 256
#define BKC 64                      // k-elems per chunk/stage
#define NQ (KDIM / BKC)             // 144
#define NITER (3 * NQ)              // 432
#define ROWPB 144                   // padded row stride bytes (64*2 + 16)
#define A_ST (TILE_M * ROWPB)       // 18432
#define B_ST (TILE_N * ROWPB)       // 36864
#define STAGE (A_ST + B_ST)         // 55296
#define NSTAGE 3
#define SMEM_TOTAL (NSTAGE * STAGE) // 165888

__device__ __forceinline__ uint32_t smem_u32(const void* p) {
    uint32_t a;
    asm("{ .reg .u64 t; cvta.to.shared.u64 t, %1; cvt.u32.u64 %0, t; }"
        : "=r"(a) : "l"(p));
    return a;
}
__device__ __forceinline__ void cp16(uint32_t dst, const void* src) {
    asm volatile("cp.async.cg.shared.global [%0], [%1], 16;" :: "r"(dst), "l"(src));
}
__device__ __forceinline__ void ldmx4(uint32_t* r, uint32_t addr) {
    asm volatile("ldmatrix.sync.aligned.m8n8.x4.shared.b16 {%0,%1,%2,%3}, [%4];"
                 : "=r"(r[0]), "=r"(r[1]), "=r"(r[2]), "=r"(r[3]) : "r"(addr));
}
__device__ __forceinline__ void mma16816(float* c, const uint32_t* a, const uint32_t* b) {
    asm volatile(
        "mma.sync.aligned.m16n8k16.row.col.f32.bf16.bf16.f32 "
        "{%0,%1,%2,%3}, {%4,%5,%6,%7}, {%8,%9}, {%0,%1,%2,%3};"
        : "+f"(c[0]), "+f"(c[1]), "+f"(c[2]), "+f"(c[3])
        : "r"(a[0]), "r"(a[1]), "r"(a[2]), "r"(a[3]), "r"(b[0]), "r"(b[1]));
}

extern __shared__ char dynsmem[];

__global__ void __launch_bounds__(512, 1) gemm_mma_kernel(float* __restrict__ out) {
    const uint32_t smem_base = smem_u32(dynsmem);
    const int tid = threadIdx.x;
    const int lane = tid & 31;
    const int warp = tid >> 5;
    const int wm = warp & 3;         // M band: 32*wm
    const int wn = warp >> 2;        // N band: 64*wn

    const int mBase = blockIdx.y * TILE_M;
    const int nBase = blockIdx.x * TILE_N;

    const __nv_bfloat16* Ah = g_Th + (size_t)mBase * KDIM;
    const __nv_bfloat16* Al = g_Tl + (size_t)mBase * KDIM;
    const __nv_bfloat16* Bh = g_Bh + (size_t)nBase * KDIM;
    const __nv_bfloat16* Bl = g_Bl + (size_t)nBase * KDIM;

    // ldmatrix lane addressing (same proven mapping as R4)
    const int aRow = (lane & 7) + ((lane >> 3) & 1) * 8;
    const int aK8  = (lane >> 4) & 1;
    const int bRow = (lane & 7) + ((lane >> 4) & 1) * 8;
    const int bK8  = (lane >> 3) & 1;

    float acc[2][8][4];
    #pragma unroll
    for (int mt = 0; mt < 2; mt++)
        #pragma unroll
        for (int nt = 0; nt < 8; nt++)
            #pragma unroll
            for (int j = 0; j < 4; j++)
                acc[mt][nt][j] = 0.0f;

    // ---- stage loader: virtual chunk kt -> (q = kt/3, phase = kt%3) -------
    auto load_stage = [&](int kt, int buf) {
        const int q = kt / 3;
        const int p = kt - 3 * q;
        const int k0 = q * BKC;
        const __nv_bfloat16* pa = (p == 2) ? Al : Ah;
        const __nv_bfloat16* pb = (p == 1) ? Bl : Bh;
        const uint32_t so = smem_base + buf * STAGE;
        // A: 128 rows x 8 chunks = 1024; 2 per thread
        #pragma unroll
        for (int r = 0; r < 2; r++) {
            int c = tid + 512 * r;
            int row = c >> 3, c16 = c & 7;
            cp16(so + row * ROWPB + c16 * 16,
                 pa + (size_t)row * KDIM + k0 + c16 * 8);
        }
        // B: 256 rows x 8 chunks = 2048; 4 per thread
        #pragma unroll
        for (int r = 0; r < 4; r++) {
            int c = tid + 512 * r;
            int row = c >> 3, c16 = c & 7;
            cp16(so + A_ST + row * ROWPB + c16 * 16,
                 pb + (size_t)row * KDIM + k0 + c16 * 8);
        }
        asm volatile("cp.async.commit_group;" ::: "memory");
    };

    load_stage(0, 0);
    load_stage(1, 1);

    for (int kt = 0; kt < NITER; kt++) {
        if (kt == NITER - 1)
            asm volatile("cp.async.wait_group 0;" ::: "memory");
        else
            asm volatile("cp.async.wait_group 1;" ::: "memory");
        __syncthreads();
        // buffer (kt+2)%3 == (kt-1)%3: everyone finished reading it (barrier)
        if (kt + 2 < NITER)
            load_stage(kt + 2, (kt + 2) % 3);

        const uint32_t so = smem_base + (kt % 3) * STAGE;
        const uint32_t aBase = so + (wm * 32 + aRow) * ROWPB + aK8 * 16;
        const uint32_t bBase = so + A_ST + (wn * 64 + bRow) * ROWPB + bK8 * 16;

        #pragma unroll
        for (int kk = 0; kk < BKC; kk += 16) {
            uint32_t af[2][4];
            uint32_t bf[8][2];
            #pragma unroll
            for (int mt = 0; mt < 2; mt++)
                ldmx4(af[mt], aBase + mt * 16 * ROWPB + kk * 2);
            #pragma unroll
            for (int nt2 = 0; nt2 < 4; nt2++) {
                uint32_t r[4];
                ldmx4(r, bBase + nt2 * 16 * ROWPB + kk * 2);
                bf[nt2 * 2 + 0][0] = r[0];
                bf[nt2 * 2 + 0][1] = r[1];
                bf[nt2 * 2 + 1][0] = r[2];
                bf[nt2 * 2 + 1][1] = r[3];
            }
            #pragma unroll
            for (int mt = 0; mt < 2; mt++)
                #pragma unroll
                for (int nt = 0; nt < 8; nt++)
                    mma16816(acc[mt][nt], af[mt], bf[nt]);
        }
    }

    // ---- epilogue ------------------------------------------------------
    const int mW = mBase + wm * 32;
    const int nW = nBase + wn * 64;
    #pragma unroll
    for (int mt = 0; mt < 2; mt++) {
        #pragma unroll
        for (int nt = 0; nt < 8; nt++) {
            int row0 = mW + mt * 16 + (lane >> 2);
            int col  = nW + nt * 8 + (lane & 3) * 2;
            *(float2*)(out + (size_t)row0 * ODIM + col) =
                make_float2(acc[mt][nt][0], acc[mt][nt][1]);
            *(float2*)(out + (size_t)(row0 + 8) * ODIM + col) =
                make_float2(acc[mt][nt][2], acc[mt][nt][3]);
        }
    }
}

// ---------------------------------------------------------------------------
extern "C" void kernel_launch(void* const* d_in, const int* in_sizes, int n_in,
                              void* d_out, int out_size) {
    const float* x = (const float*)d_in[0];
    const float* coeffs = (const float*)d_in[1];
    float* out = (float*)d_out;

    int nb = in_sizes[0] / IDIM;   // 8192

    cudaFuncSetAttribute(gemm_mma_kernel,
                         cudaFuncAttributeMaxDynamicSharedMemorySize, SMEM_TOTAL);

    buildT_kernel<<<nb, 256>>>(x);
    transC_kernel<<<(ODIM * (IDIM / 2) + 255) / 256, 256>>>(coeffs);

    dim3 grid(ODIM / TILE_N, nb / TILE_M);   // (4, 64)
    gemm_mma_kernel<<<grid, 512, SMEM_TOTAL>>>(out);
}

// round 8
// speedup vs baseline: 2.8461x; 1.1454x over previous
#include <cuda_runtime.h>
#include <cuda_bf16.h>
#include <cstdint>

#define IDIM 1024
#define ODIM 1024
#define NDEG 9
#define KDIM (IDIM*NDEG)   // 9216, k = j*1024 + i
#define BMAX 8192

// ---------------- device scratch (static globals: allocation-guard safe) ----
__device__ __nv_bfloat16 g_Th[(size_t)BMAX * KDIM];   // A hi  [M][K]
__device__ __nv_bfloat16 g_Tl[(size_t)BMAX * KDIM];   // A lo  [M][K]
__device__ __nv_bfloat16 g_Bh[(size_t)ODIM * KDIM];   // B hi  [N][K]
__device__ __nv_bfloat16 g_Bl[(size_t)ODIM * KDIM];   // B lo  [N][K]

// ---------------------------------------------------------------------------
// Kernel 1: fused row min/max + Chebyshev basis (hi/lo bf16), K = j*1024 + i
// ---------------------------------------------------------------------------
__global__ void __launch_bounds__(256) buildT_kernel(const float* __restrict__ x) {
    const int b = blockIdx.x;
    const int tid = threadIdx.x;
    const float* row = x + (size_t)b * IDIM;

    float2 v[2];
    #pragma unroll
    for (int s = 0; s < 2; s++)
        v[s] = *(const float2*)(row + 2 * (tid + 256 * s));

    float mn = fminf(fminf(v[0].x, v[0].y), fminf(v[1].x, v[1].y));
    float mx = fmaxf(fmaxf(v[0].x, v[0].y), fmaxf(v[1].x, v[1].y));
    #pragma unroll
    for (int o = 16; o; o >>= 1) {
        mn = fminf(mn, __shfl_xor_sync(0xFFFFFFFFu, mn, o));
        mx = fmaxf(mx, __shfl_xor_sync(0xFFFFFFFFu, mx, o));
    }
    __shared__ float smn[8], smx[8];
    int w = tid >> 5, l = tid & 31;
    if (l == 0) { smn[w] = mn; smx[w] = mx; }
    __syncthreads();
    #pragma unroll
    for (int i = 0; i < 8; i++) { mn = fminf(mn, smn[i]); mx = fmaxf(mx, smx[i]); }
    const float sc = 2.0f / (mx - mn);

    const size_t base = (size_t)b * KDIM;
    #pragma unroll
    for (int s = 0; s < 2; s++) {
        int p = tid + 256 * s;
        float xa = (v[s].x - mn) * sc - 1.0f;
        float xb = (v[s].y - mn) * sc - 1.0f;
        float a0 = 1.0f, a1 = xa, b0 = 1.0f, b1 = xb;
        #pragma unroll
        for (int j = 0; j < NDEG; j++) {
            float ta = (j == 0) ? 1.0f : a1;
            float tb = (j == 0) ? 1.0f : b1;
            __nv_bfloat16 ha = __float2bfloat16(ta);
            __nv_bfloat16 hb = __float2bfloat16(tb);
            __nv_bfloat162 hi2, lo2;
            hi2.x = ha; hi2.y = hb;
            lo2.x = __float2bfloat16(ta - __bfloat162float(ha));
            lo2.y = __float2bfloat16(tb - __bfloat162float(hb));
            size_t off = base + (size_t)j * IDIM + 2 * p;
            *(__nv_bfloat162*)(g_Th + off) = hi2;
            *(__nv_bfloat162*)(g_Tl + off) = lo2;
            if (j >= 1) {
                float na = 2.0f * xa * a1 - a0; a0 = a1; a1 = na;
                float nb = 2.0f * xb * b1 - b0; b0 = b1; b1 = nb;
            }
        }
    }
}

// ---------------------------------------------------------------------------
// Kernel 2: coeffs [i][o][j] -> B[o][k=j*1024+i], hi/lo bf16
// ---------------------------------------------------------------------------
__global__ void transC_kernel(const float* __restrict__ c) {
    int idx = blockIdx.x * blockDim.x + threadIdx.x;
    if (idx >= ODIM * (IDIM / 2)) return;
    int o = idx >> 9;
    int p = idx & 511;
    const float* s0 = c + ((size_t)(2 * p) * ODIM + o) * NDEG;
    const float* s1 = c + ((size_t)(2 * p + 1) * ODIM + o) * NDEG;
    size_t base = (size_t)o * KDIM + 2 * p;
    #pragma unroll
    for (int j = 0; j < NDEG; j++) {
        float va = s0[j], vb = s1[j];
        __nv_bfloat16 ha = __float2bfloat16(va);
        __nv_bfloat16 hb = __float2bfloat16(vb);
        __nv_bfloat162 hi2, lo2;
        hi2.x = ha; hi2.y = hb;
        lo2.x = __float2bfloat16(va - __bfloat162float(ha));
        lo2.y = __float2bfloat16(vb - __bfloat162float(hb));
        size_t off = base + (size_t)j * IDIM;
        *(__nv_bfloat162*)(g_Bh + off) = hi2;
        *(__nv_bfloat162*)(g_Bl + off) = lo2;
    }
}

// ---------------------------------------------------------------------------
// Kernel 3: mma.sync bf16 GEMM, CTA 128x256, 512 thr, warp 32x64
// All 4 split-tiles loaded once per q; 3 split-GEMMs reuse fragments.
// ---------------------------------------------------------------------------
#define TILE_M 128
#define TILE_N 256
#define BKC 64                      // K elems per stage
#define NQ (KDIM / BKC)             // 144
#define ROWPB 144                   // padded row stride bytes
#define A_ST (TILE_M * ROWPB)       // 18432  (one A split)
#define B_ST (TILE_N * ROWPB)       // 36864  (one B split)
#define STAGE (2*A_ST + 2*B_ST)     // 110592
#define SMEM_TOTAL (2 * STAGE)      // 221184

__device__ __forceinline__ uint32_t smem_u32(const void* p) {
    uint32_t a;
    asm("{ .reg .u64 t; cvta.to.shared.u64 t, %1; cvt.u32.u64 %0, t; }"
        : "=r"(a) : "l"(p));
    return a;
}
__device__ __forceinline__ void cp16(uint32_t dst, const void* src) {
    asm volatile("cp.async.cg.shared.global [%0], [%1], 16;" :: "r"(dst), "l"(src));
}
__device__ __forceinline__ void ldmx4(uint32_t* r, uint32_t addr) {
    asm volatile("ldmatrix.sync.aligned.m8n8.x4.shared.b16 {%0,%1,%2,%3}, [%4];"
                 : "=r"(r[0]), "=r"(r[1]), "=r"(r[2]), "=r"(r[3]) : "r"(addr));
}
__device__ __forceinline__ void mma16816(float* c, const uint32_t* a, const uint32_t* b) {
    asm volatile(
        "mma.sync.aligned.m16n8k16.row.col.f32.bf16.bf16.f32 "
        "{%0,%1,%2,%3}, {%4,%5,%6,%7}, {%8,%9}, {%0,%1,%2,%3};"
        : "+f"(c[0]), "+f"(c[1]), "+f"(c[2]), "+f"(c[3])
        : "r"(a[0]), "r"(a[1]), "r"(a[2]), "r"(a[3]), "r"(b[0]), "r"(b[1]));
}

extern __shared__ char dynsmem[];

__global__ void __launch_bounds__(512, 1) gemm_mma_kernel(float* __restrict__ out) {
    const uint32_t smem_base = smem_u32(dynsmem);
    const int tid = threadIdx.x;
    const int lane = tid & 31;
    const int warp = tid >> 5;
    const int wm = warp & 3;         // M band: 32*wm
    const int wn = warp >> 2;        // N band: 64*wn

    const int mBase = blockIdx.y * TILE_M;
    const int nBase = blockIdx.x * TILE_N;

    const __nv_bfloat16* Ah = g_Th + (size_t)mBase * KDIM;
    const __nv_bfloat16* Al = g_Tl + (size_t)mBase * KDIM;
    const __nv_bfloat16* Bh = g_Bh + (size_t)nBase * KDIM;
    const __nv_bfloat16* Bl = g_Bl + (size_t)nBase * KDIM;

    const int aRow = (lane & 7) + ((lane >> 3) & 1) * 8;
    const int aK8  = (lane >> 4) & 1;
    const int bRow = (lane & 7) + ((lane >> 4) & 1) * 8;
    const int bK8  = (lane >> 3) & 1;

    float acc[2][8][4];
    #pragma unroll
    for (int mt = 0; mt < 2; mt++)
        #pragma unroll
        for (int nt = 0; nt < 8; nt++)
            #pragma unroll
            for (int j = 0; j < 4; j++)
                acc[mt][nt][j] = 0.0f;

    // ---- stage loader: all 4 split-tiles for K-chunk q --------------------
    auto load_stage = [&](int q, int buf) {
        const int k0 = q * BKC;
        const uint32_t so = smem_base + buf * STAGE;
        // A: 2 splits x 128 rows x 8 chunks = 2048; 4/thread
        #pragma unroll
        for (int r = 0; r < 4; r++) {
            int c = tid + 512 * r;
            int s = c >> 10, row = (c >> 3) & 127, c16 = c & 7;
            const __nv_bfloat16* pa = s ? Al : Ah;
            cp16(so + s * A_ST + row * ROWPB + c16 * 16,
                 pa + (size_t)row * KDIM + k0 + c16 * 8);
        }
        // B: 2 splits x 256 rows x 8 chunks = 4096; 8/thread
        #pragma unroll
        for (int r = 0; r < 8; r++) {
            int c = tid + 512 * r;
            int s = c >> 11, row = (c >> 3) & 255, c16 = c & 7;
            const __nv_bfloat16* pb = s ? Bl : Bh;
            cp16(so + 2 * A_ST + s * B_ST + row * ROWPB + c16 * 16,
                 pb + (size_t)row * KDIM + k0 + c16 * 8);
        }
        asm volatile("cp.async.commit_group;" ::: "memory");
    };

    load_stage(0, 0);

    for (int q = 0; q < NQ; q++) {
        if (q + 1 < NQ) {
            load_stage(q + 1, (q + 1) & 1);
            asm volatile("cp.async.wait_group 1;" ::: "memory");
        } else {
            asm volatile("cp.async.wait_group 0;" ::: "memory");
        }
        __syncthreads();

        const uint32_t so = smem_base + (q & 1) * STAGE;
        const uint32_t aBaseH = so + (wm * 32 + aRow) * ROWPB + aK8 * 16;
        const uint32_t aBaseL = aBaseH + A_ST;
        const uint32_t bBaseH = so + 2 * A_ST + (wn * 64 + bRow) * ROWPB + bK8 * 16;
        const uint32_t bBaseL = bBaseH + B_ST;

        #pragma unroll
        for (int kk = 0; kk < BKC; kk += 16) {
            uint32_t ah[2][4], al[2][4];
            uint32_t bh[8][2], bl[8][2];
            // hh
            #pragma unroll
            for (int mt = 0; mt < 2; mt++)
                ldmx4(ah[mt], aBaseH + mt * 16 * ROWPB + kk * 2);
            #pragma unroll
            for (int nt2 = 0; nt2 < 4; nt2++) {
                uint32_t r[4];
                ldmx4(r, bBaseH + nt2 * 16 * ROWPB + kk * 2);
                bh[nt2*2+0][0] = r[0]; bh[nt2*2+0][1] = r[1];
                bh[nt2*2+1][0] = r[2]; bh[nt2*2+1][1] = r[3];
            }
            #pragma unroll
            for (int mt = 0; mt < 2; mt++)
                #pragma unroll
                for (int nt = 0; nt < 8; nt++)
                    mma16816(acc[mt][nt], ah[mt], bh[nt]);
            // hl (Ah x Bl)
            #pragma unroll
            for (int nt2 = 0; nt2 < 4; nt2++) {
                uint32_t r[4];
                ldmx4(r, bBaseL + nt2 * 16 * ROWPB + kk * 2);
                bl[nt2*2+0][0] = r[0]; bl[nt2*2+0][1] = r[1];
                bl[nt2*2+1][0] = r[2]; bl[nt2*2+1][1] = r[3];
            }
            #pragma unroll
            for (int mt = 0; mt < 2; mt++)
                #pragma unroll
                for (int nt = 0; nt < 8; nt++)
                    mma16816(acc[mt][nt], ah[mt], bl[nt]);
            // lh (Al x Bh)
            #pragma unroll
            for (int mt = 0; mt < 2; mt++)
                ldmx4(al[mt], aBaseL + mt * 16 * ROWPB + kk * 2);
            #pragma unroll
            for (int mt = 0; mt < 2; mt++)
                #pragma unroll
                for (int nt = 0; nt < 8; nt++)
                    mma16816(acc[mt][nt], al[mt], bh[nt]);
        }
        __syncthreads();
    }

    // ---- epilogue ------------------------------------------------------
    const int mW = mBase + wm * 32;
    const int nW = nBase + wn * 64;
    #pragma unroll
    for (int mt = 0; mt < 2; mt++) {
        #pragma unroll
        for (int nt = 0; nt < 8; nt++) {
            int row0 = mW + mt * 16 + (lane >> 2);
            int col  = nW + nt * 8 + (lane & 3) * 2;
            *(float2*)(out + (size_t)row0 * ODIM + col) =
                make_float2(acc[mt][nt][0], acc[mt][nt][1]);
            *(float2*)(out + (size_t)(row0 + 8) * ODIM + col) =
                make_float2(acc[mt][nt][2], acc[mt][nt][3]);
        }
    }
}

// ---------------------------------------------------------------------------
extern "C" void kernel_launch(void* const* d_in, const int* in_sizes, int n_in,
                              void* d_out, int out_size) {
    const float* x = (const float*)d_in[0];
    const float* coeffs = (const float*)d_in[1];
    float* out = (float*)d_out;

    int nb = in_sizes[0] / IDIM;   // 8192

    cudaFuncSetAttribute(gemm_mma_kernel,
                         cudaFuncAttributeMaxDynamicSharedMemorySize, SMEM_TOTAL);

    buildT_kernel<<<nb, 256>>>(x);
    transC_kernel<<<(ODIM * (IDIM / 2) + 255) / 256, 256>>>(coeffs);

    dim3 grid(ODIM / TILE_N, nb / TILE_M);   // (4, 64)
    gemm_mma_kernel<<<grid, 512, SMEM_TOTAL>>>(out);
}